// round 15
// baseline (speedup 1.0000x reference)
#include <cuda_runtime.h>
#include <cuda_bf16.h>
#include <math.h>
#include <stdint.h>

#define NN 50000
#define EE 800000
#define DD 256
#define HH 4
#define HC 256      // H*C
#define OUTC 5
#define FHC 20      // H*OUT

// ---------------- scratch (static device globals) ----------------
__device__ float g_xl[(size_t)NN * HC];
__device__ float g_xr[(size_t)NN * HC];
__device__ float g_lin[(size_t)NN * HC];
__device__ float g_agg[(size_t)NN * HC];
__device__ float g_emb[(size_t)NN * HC];
__device__ float g_stats[4 * HC];          // 2 layers x (sum, sumsq)
__device__ int   g_rowptr[NN + 1];
__device__ int   g_cnt[NN];
__device__ int   g_elist[EE];
__device__ __nv_bfloat16 g_ahi[(size_t)NN * DD];
__device__ __nv_bfloat16 g_alo[(size_t)NN * DD];
__device__ __nv_bfloat16 g_bthi[6 * DD * HC];
__device__ __nv_bfloat16 g_btlo[6 * DD * HC];

// ---------------- CSR build ----------------
__global__ void hist_kernel(const int* __restrict__ dst, int* __restrict__ cnt) {
    int e = blockIdx.x * blockDim.x + threadIdx.x;
    if (e < EE) atomicAdd(&cnt[dst[e]], 1);
}

__global__ void scan_kernel(const int* __restrict__ cnt, int* __restrict__ rowptr) {
    __shared__ int sh[1024];
    __shared__ int offs;
    if (threadIdx.x == 0) { offs = 0; rowptr[0] = 0; }
    __syncthreads();
    for (int base = 0; base < NN; base += 1024) {
        int i = base + threadIdx.x;
        int v = (i < NN) ? cnt[i] : 0;
        sh[threadIdx.x] = v;
        __syncthreads();
        #pragma unroll
        for (int off = 1; off < 1024; off <<= 1) {
            int t = (threadIdx.x >= off) ? sh[threadIdx.x - off] : 0;
            __syncthreads();
            sh[threadIdx.x] += t;
            __syncthreads();
        }
        if (i < NN) rowptr[i + 1] = sh[threadIdx.x] + offs;
        __syncthreads();
        if (threadIdx.x == 1023) offs += sh[1023];
        __syncthreads();
    }
}

__global__ void scatter_kernel(const int* __restrict__ src, const int* __restrict__ dst,
                               const int* __restrict__ rowptr, int* __restrict__ cnt,
                               int* __restrict__ elist) {
    int e = blockIdx.x * blockDim.x + threadIdx.x;
    if (e >= EE) return;
    int d = dst[e];
    int pos = rowptr[d] + atomicAdd(&cnt[d], 1);
    elist[pos] = src[e];
}

// ---------------- bf16 split kernels ----------------
__global__ void split_a_kernel(const float* __restrict__ A,
                               __nv_bfloat16* __restrict__ hi, __nv_bfloat16* __restrict__ lo,
                               int n) {
    int i = blockIdx.x * blockDim.x + threadIdx.x;
    if (i >= n) return;
    float v = A[i];
    __nv_bfloat16 h = __float2bfloat16(v);
    hi[i] = h;
    lo[i] = __float2bfloat16(v - __bfloat162float(h));
}

__global__ void split_bt6_kernel(const float* __restrict__ Wl, const float* __restrict__ Wr,
                                 const float* __restrict__ Wlin,
                                 __nv_bfloat16* __restrict__ hi, __nv_bfloat16* __restrict__ lo) {
    int i = blockIdx.x * blockDim.x + threadIdx.x;   // 65536
    int m = blockIdx.y;                               // 0..5
    int layer = m / 3, which = m % 3;
    const float* B = (which == 0) ? Wl : (which == 1) ? Wr : Wlin;
    B += (size_t)layer * DD * HC;
    int k = i >> 8, n = i & 255;
    float v = B[k * 256 + n];
    __nv_bfloat16 h = __float2bfloat16(v);
    size_t o = (size_t)m * DD * HC + (size_t)n * 256 + k;
    hi[o] = h;
    lo[o] = __float2bfloat16(v - __bfloat162float(h));
}

// ---------------- mma.sync helpers ----------------
__device__ __forceinline__ void mma_bf16(float* d, const uint32_t* a, uint32_t b0, uint32_t b1) {
    asm volatile(
        "mma.sync.aligned.m16n8k16.row.col.f32.bf16.bf16.f32 "
        "{%0,%1,%2,%3}, {%4,%5,%6,%7}, {%8,%9}, {%0,%1,%2,%3};"
        : "+f"(d[0]), "+f"(d[1]), "+f"(d[2]), "+f"(d[3])
        : "r"(a[0]), "r"(a[1]), "r"(a[2]), "r"(a[3]), "r"(b0), "r"(b1));
}
__device__ __forceinline__ void ldsm4a(uint32_t* r, uint32_t addr) {
    asm volatile("ldmatrix.sync.aligned.m8n8.x4.shared.b16 {%0,%1,%2,%3}, [%4];"
        : "=r"(r[0]), "=r"(r[1]), "=r"(r[2]), "=r"(r[3]) : "r"(addr));
}
__device__ __forceinline__ void cp16(uint32_t dst, const void* src, bool pred) {
    int sz = pred ? 16 : 0;
    asm volatile("cp.async.cg.shared.global [%0], [%1], 16, %2;"
                 :: "r"(dst), "l"(src), "r"(sz));
}
__device__ __forceinline__ void cp_commit() {
    asm volatile("cp.async.commit_group;" ::: "memory");
}
template <int N>
__device__ __forceinline__ void cp_wait() {
    asm volatile("cp.async.wait_group %0;" :: "n"(N) : "memory");
}

// ---------------- GEMM: fused N=768, 128x128 tiles, cp.async, KT=32, 3xBF16 ----------------
#define ROWB 80
#define OFF_ALO (128 * ROWB)
#define OFF_BHI (2 * 128 * ROWB)
#define OFF_BLO (3 * 128 * ROWB)
#define STAGE_B (4 * 128 * ROWB)      // 40960
#define GSM_TOTAL (2 * STAGE_B)       // 81920

__global__ __launch_bounds__(256, 2) void gemm_wide(
    const __nv_bfloat16* __restrict__ Ahi, const __nv_bfloat16* __restrict__ Alo,
    const __nv_bfloat16* __restrict__ Bthi, const __nv_bfloat16* __restrict__ Btlo,
    const float* __restrict__ blin,
    float* __restrict__ C0, float* __restrict__ C1, float* __restrict__ C2, int M)
{
    extern __shared__ char smraw[];
    const uint32_t sb = (uint32_t)__cvta_generic_to_shared(smraw);

    const int tid = threadIdx.x;
    const int bx = blockIdx.x, by = blockIdx.y;
    const int n0 = bx * 128;
    const int mat = n0 >> 8;
    const int cbase = n0 & 255;
    float* C = (mat == 0) ? C0 : (mat == 1) ? C1 : C2;

    const __nv_bfloat16* Bh = Bthi + (size_t)n0 * DD;
    const __nv_bfloat16* Bl = Btlo + (size_t)n0 * DD;

    const int lane = tid & 31, wid = tid >> 5;
    const int warpM = wid >> 1;
    const int warpN = wid & 1;
    const int g = lane >> 2, t = lane & 3;
    const int lr = lane & 15;
    const uint32_t lkB = (uint32_t)((lane >> 4) * 16);

    const int ldRow = tid >> 1;
    const int ldHalf = (tid & 1) * 32;

    const int gARow = by * 128 + ldRow;
    const bool aOK = (gARow < M);
    const __nv_bfloat16* Aph = Ahi + (size_t)gARow * DD;
    const __nv_bfloat16* Apl = Alo + (size_t)gARow * DD;
    const __nv_bfloat16* Bph = Bh + (size_t)ldRow * DD;
    const __nv_bfloat16* Bpl = Bl + (size_t)ldRow * DD;

    float acc[2][8][4];
    #pragma unroll
    for (int mi = 0; mi < 2; mi++)
        #pragma unroll
        for (int ni = 0; ni < 8; ni++)
            #pragma unroll
            for (int r = 0; r < 4; r++) acc[mi][ni][r] = 0.f;

    auto issue = [&](int kt, int stage) {
        const int k0 = kt * 32;
        const uint32_t s = sb + (uint32_t)stage * STAGE_B;
        uint32_t roff = (uint32_t)(ldRow * ROWB + ldHalf);
        const int ke = k0 + ldHalf / 2;
        cp16(s + roff,                Aph + ke,     aOK);
        cp16(s + roff + 16,           Aph + ke + 8, aOK);
        cp16(s + OFF_ALO + roff,      Apl + ke,     aOK);
        cp16(s + OFF_ALO + roff + 16, Apl + ke + 8, aOK);
        cp16(s + OFF_BHI + roff,      Bph + ke,     true);
        cp16(s + OFF_BHI + roff + 16, Bph + ke + 8, true);
        cp16(s + OFF_BLO + roff,      Bpl + ke,     true);
        cp16(s + OFF_BLO + roff + 16, Bpl + ke + 8, true);
        cp_commit();
    };

    issue(0, 0);

    const int NT = DD / 32;   // 8
    for (int kt = 0; kt < NT; kt++) {
        const int cur = kt & 1;
        cp_wait<0>();
        __syncthreads();
        if (kt + 1 < NT) issue(kt + 1, (kt + 1) & 1);   // overlaps with compute below

        const uint32_t s = sb + (uint32_t)cur * STAGE_B;
        #pragma unroll
        for (int ks2 = 0; ks2 < 2; ks2++) {
            const uint32_t kb = (uint32_t)(ks2 * 32) + lkB;
            uint32_t ah[2][4], al[2][4];
            #pragma unroll
            for (int mi = 0; mi < 2; mi++) {
                uint32_t r = (uint32_t)((warpM * 32 + mi * 16 + lr) * ROWB) + kb;
                ldsm4a(ah[mi], s + r);
                ldsm4a(al[mi], s + OFF_ALO + r);
            }
            #pragma unroll
            for (int p = 0; p < 4; p++) {
                uint32_t r = (uint32_t)((warpN * 64 + p * 16 + lr) * ROWB) + kb;
                uint32_t th[4], tl[4];
                ldsm4a(th, s + OFF_BHI + r);
                ldsm4a(tl, s + OFF_BLO + r);
                #pragma unroll
                for (int mi = 0; mi < 2; mi++) {
                    mma_bf16(acc[mi][2 * p],     ah[mi], th[0], th[2]);
                    mma_bf16(acc[mi][2 * p],     ah[mi], tl[0], tl[2]);
                    mma_bf16(acc[mi][2 * p],     al[mi], th[0], th[2]);
                    mma_bf16(acc[mi][2 * p + 1], ah[mi], th[1], th[3]);
                    mma_bf16(acc[mi][2 * p + 1], ah[mi], tl[1], tl[3]);
                    mma_bf16(acc[mi][2 * p + 1], al[mi], th[1], th[3]);
                }
            }
        }
    }

    #pragma unroll
    for (int mi = 0; mi < 2; mi++) {
        int r0 = by * 128 + warpM * 32 + mi * 16 + g;
        #pragma unroll
        for (int ni = 0; ni < 8; ni++) {
            int ccol = cbase + warpN * 64 + ni * 8 + t * 2;
            float b0 = (mat == 2) ? blin[ccol] : 0.f;
            float b1 = (mat == 2) ? blin[ccol + 1] : 0.f;
            if (r0 < M)
                *(float2*)(C + (size_t)r0 * 256 + ccol) =
                    make_float2(acc[mi][ni][0] + b0, acc[mi][ni][1] + b1);
            if (r0 + 8 < M)
                *(float2*)(C + (size_t)(r0 + 8) * 256 + ccol) =
                    make_float2(acc[mi][ni][2] + b0, acc[mi][ni][3] + b1);
        }
    }
}

// ---------------- CSR node-centric attention (warp per dst node) + fused stats ----------------
__global__ __launch_bounds__(256) void node_attn_kernel(
    const float* __restrict__ xl, const float* __restrict__ xr,
    const float* __restrict__ att,
    const int* __restrict__ rowptr, const int* __restrict__ elist,
    float* __restrict__ aggout, float* __restrict__ stats)
{
    __shared__ float sstat[2][HC];
    for (int i = threadIdx.x; i < 2 * HC; i += 256) ((float*)sstat)[i] = 0.f;
    __syncthreads();

    int n = (blockIdx.x * blockDim.x + threadIdx.x) >> 5;
    int lane = threadIdx.x & 31;
    const int base = lane * 8;

    float xrv[8], attv[8];
    {
        const float4* p = (const float4*)(xr + (size_t)n * HC + base);
        float4 r0 = p[0], r1 = p[1];
        xrv[0] = r0.x; xrv[1] = r0.y; xrv[2] = r0.z; xrv[3] = r0.w;
        xrv[4] = r1.x; xrv[5] = r1.y; xrv[6] = r1.z; xrv[7] = r1.w;
        const float4* q = (const float4*)(att + base);
        float4 a0 = q[0], a1 = q[1];
        attv[0] = a0.x; attv[1] = a0.y; attv[2] = a0.z; attv[3] = a0.w;
        attv[4] = a1.x; attv[5] = a1.y; attv[6] = a1.z; attv[7] = a1.w;
    }

    float acc[8] = {0.f, 0.f, 0.f, 0.f, 0.f, 0.f, 0.f, 0.f};
    float dn = 0.f;
    const int s0 = rowptr[n], s1 = rowptr[n + 1];
    int i = s0;
    for (; i + 3 < s1; i += 4) {
        int e0 = elist[i], e1 = elist[i + 1], e2 = elist[i + 2], e3 = elist[i + 3];
        const float4* p0 = (const float4*)(xl + (size_t)e0 * HC + base);
        const float4* p1 = (const float4*)(xl + (size_t)e1 * HC + base);
        const float4* p2 = (const float4*)(xl + (size_t)e2 * HC + base);
        const float4* p3 = (const float4*)(xl + (size_t)e3 * HC + base);
        float4 a0 = p0[0], b0 = p0[1];
        float4 a1 = p1[0], b1 = p1[1];
        float4 a2 = p2[0], b2 = p2[1];
        float4 a3 = p3[0], b3 = p3[1];
        float x0[8] = {a0.x, a0.y, a0.z, a0.w, b0.x, b0.y, b0.z, b0.w};
        float x1[8] = {a1.x, a1.y, a1.z, a1.w, b1.x, b1.y, b1.z, b1.w};
        float x2[8] = {a2.x, a2.y, a2.z, a2.w, b2.x, b2.y, b2.z, b2.w};
        float x3[8] = {a3.x, a3.y, a3.z, a3.w, b3.x, b3.y, b3.z, b3.w};
        float c0 = 0.f, c1 = 0.f, c2 = 0.f, c3 = 0.f;
        #pragma unroll
        for (int t = 0; t < 8; t++) {
            float v;
            v = x0[t] + xrv[t]; v = v > 0.f ? v : 0.2f * v; c0 += v * attv[t];
            v = x1[t] + xrv[t]; v = v > 0.f ? v : 0.2f * v; c1 += v * attv[t];
            v = x2[t] + xrv[t]; v = v > 0.f ? v : 0.2f * v; c2 += v * attv[t];
            v = x3[t] + xrv[t]; v = v > 0.f ? v : 0.2f * v; c3 += v * attv[t];
        }
        #pragma unroll
        for (int d = 4; d >= 1; d >>= 1) {
            c0 += __shfl_xor_sync(0xffffffffu, c0, d);
            c1 += __shfl_xor_sync(0xffffffffu, c1, d);
            c2 += __shfl_xor_sync(0xffffffffu, c2, d);
            c3 += __shfl_xor_sync(0xffffffffu, c3, d);
        }
        float w0 = __expf(c0), w1 = __expf(c1), w2 = __expf(c2), w3 = __expf(c3);
        dn += (w0 + w1) + (w2 + w3);
        #pragma unroll
        for (int t = 0; t < 8; t++)
            acc[t] += (w0 * x0[t] + w1 * x1[t]) + (w2 * x2[t] + w3 * x3[t]);
    }
    for (; i < s1; i++) {
        int e0 = elist[i];
        const float4* p = (const float4*)(xl + (size_t)e0 * HC + base);
        float4 a0 = p[0], b0 = p[1];
        float x0[8] = {a0.x, a0.y, a0.z, a0.w, b0.x, b0.y, b0.z, b0.w};
        float sc = 0.f;
        #pragma unroll
        for (int t = 0; t < 8; t++) {
            float v = x0[t] + xrv[t];
            v = v > 0.f ? v : 0.2f * v;
            sc += v * attv[t];
        }
        sc += __shfl_xor_sync(0xffffffffu, sc, 4);
        sc += __shfl_xor_sync(0xffffffffu, sc, 2);
        sc += __shfl_xor_sync(0xffffffffu, sc, 1);
        float e = __expf(sc);
        dn += e;
        #pragma unroll
        for (int t = 0; t < 8; t++) acc[t] += e * x0[t];
    }

    float inv = 1.f / (dn + 1e-16f);
    float o[8];
    #pragma unroll
    for (int t = 0; t < 8; t++) o[t] = acc[t] * inv;

    float4* op = (float4*)(aggout + (size_t)n * HC + base);
    op[0] = make_float4(o[0], o[1], o[2], o[3]);
    op[1] = make_float4(o[4], o[5], o[6], o[7]);

    #pragma unroll
    for (int t = 0; t < 8; t++) {
        atomicAdd(&sstat[0][base + t], o[t]);
        atomicAdd(&sstat[1][base + t], o[t] * o[t]);
    }
    __syncthreads();
    for (int c = threadIdx.x; c < HC; c += 256) {
        atomicAdd(&stats[c], sstat[0][c]);
        atomicAdd(&stats[HC + c], sstat[1][c]);
    }
}

// ---------------- GraphNorm epilogue ----------------
__global__ void norm_elu_kernel(
    const float* __restrict__ agg, const float* __restrict__ lin,
    const float* __restrict__ bias, const float* __restrict__ gw,
    const float* __restrict__ gb, const float* __restrict__ ms,
    const float* __restrict__ stats, float* __restrict__ out,
    __nv_bfloat16* __restrict__ hi, __nv_bfloat16* __restrict__ lo, int writeSplit)
{
    int idx = blockIdx.x * blockDim.x + threadIdx.x;
    if (idx >= NN * HC) return;
    int c = idx & 255;
    const float invn = 1.f / (float)NN;
    float b = bias[c];
    float s1 = stats[c] * invn;
    float s2 = stats[HC + c] * invn;
    float mean = s1 + b;
    float ey2 = s2 + 2.f * b * s1 + b * b;
    float msv = ms[c];
    float var = ey2 - 2.f * mean * msv * mean + mean * mean * msv * msv;
    float y = agg[idx] + b;
    float centered = y - mean * msv;
    float v = gw[c] * centered * rsqrtf(var + 1e-5f) + gb[c] + lin[idx];
    v = v > 0.f ? v : expm1f(v);
    out[idx] = v;
    if (writeSplit) {
        __nv_bfloat16 h = __float2bfloat16(v);
        hi[idx] = h;
        lo[idx] = __float2bfloat16(v - __bfloat162float(h));
    }
}

// ---------------- fused final projections (45 cols) ----------------
__global__ __launch_bounds__(256) void final_proj_kernel(
    const float* __restrict__ emb, const float* __restrict__ fWl,
    const float* __restrict__ fWr, const float* __restrict__ fWlin,
    const float* __restrict__ fblin,
    float* __restrict__ xl, float* __restrict__ xr, float* __restrict__ lin)
{
    __shared__ float Bs[DD][45];
    for (int i = threadIdx.x; i < DD * FHC; i += 256) {
        int k = i / FHC, c = i % FHC;
        Bs[k][c] = fWl[i];
        Bs[k][FHC + c] = fWr[i];
    }
    for (int i = threadIdx.x; i < DD * OUTC; i += 256) {
        int k = i / OUTC, c = i % OUTC;
        Bs[k][2 * FHC + c] = fWlin[i];
    }
    __syncthreads();

    int lane = threadIdx.x & 31;
    int warp = threadIdx.x >> 5;
    int nwarp = gridDim.x * 8;
    for (int row = blockIdx.x * 8 + warp; row < NN; row += nwarp) {
        float acc[45];
        #pragma unroll
        for (int c = 0; c < 45; c++) acc[c] = 0.f;
        #pragma unroll
        for (int i = 0; i < 8; i++) {
            float a = emb[(size_t)row * DD + i * 32 + lane];
            const float* bp = &Bs[i * 32 + lane][0];
            #pragma unroll
            for (int c = 0; c < 45; c++) acc[c] += a * bp[c];
        }
        #pragma unroll
        for (int c = 0; c < 45; c++) {
            float v = acc[c];
            v += __shfl_xor_sync(0xffffffffu, v, 16);
            v += __shfl_xor_sync(0xffffffffu, v, 8);
            v += __shfl_xor_sync(0xffffffffu, v, 4);
            v += __shfl_xor_sync(0xffffffffu, v, 2);
            v += __shfl_xor_sync(0xffffffffu, v, 1);
            acc[c] = v;
        }
        if (lane == 0) {
            #pragma unroll
            for (int c = 0; c < FHC; c++) xl[(size_t)row * FHC + c] = acc[c];
            #pragma unroll
            for (int c = 0; c < FHC; c++) xr[(size_t)row * FHC + c] = acc[FHC + c];
            #pragma unroll
            for (int c = 0; c < OUTC; c++) lin[(size_t)row * OUTC + c] = acc[2 * FHC + c] + fblin[c];
        }
    }
}

// ---------------- fused final attention + head-mean + log_softmax (thread per node) ----------------
__global__ void final_fused_kernel(
    const float* __restrict__ fxl, const float* __restrict__ fxr,
    const float* __restrict__ fatt,
    const int* __restrict__ rowptr, const int* __restrict__ elist,
    const float* __restrict__ lin, const float* __restrict__ fbconv,
    float* __restrict__ out)
{
    int n = blockIdx.x * blockDim.x + threadIdx.x;
    if (n >= NN) return;

    // hoist lin row (overlaps the gather loop below)
    float linv[OUTC];
    #pragma unroll
    for (int c = 0; c < OUTC; c++) linv[c] = lin[(size_t)n * OUTC + c];

    float xrv[FHC], attv[FHC];
    {
        const float4* p = (const float4*)(fxr + (size_t)n * FHC);
        const float4* q = (const float4*)fatt;
        #pragma unroll
        for (int j = 0; j < 5; j++) {
            float4 a = p[j], b = q[j];
            xrv[j * 4 + 0] = a.x; xrv[j * 4 + 1] = a.y; xrv[j * 4 + 2] = a.z; xrv[j * 4 + 3] = a.w;
            attv[j * 4 + 0] = b.x; attv[j * 4 + 1] = b.y; attv[j * 4 + 2] = b.z; attv[j * 4 + 3] = b.w;
        }
    }

    float acc[FHC];
    #pragma unroll
    for (int c = 0; c < FHC; c++) acc[c] = 0.f;
    float dn[HH] = {0.f, 0.f, 0.f, 0.f};

    const int s0 = rowptr[n], s1 = rowptr[n + 1];
    int i = s0;
    for (; i + 1 < s1; i += 2) {
        int sA = elist[i], sB = elist[i + 1];
        float xA[FHC], xB[FHC];
        const float4* pA = (const float4*)(fxl + (size_t)sA * FHC);
        const float4* pB = (const float4*)(fxl + (size_t)sB * FHC);
        #pragma unroll
        for (int j = 0; j < 5; j++) {
            float4 a = pA[j], b = pB[j];
            xA[j * 4 + 0] = a.x; xA[j * 4 + 1] = a.y; xA[j * 4 + 2] = a.z; xA[j * 4 + 3] = a.w;
            xB[j * 4 + 0] = b.x; xB[j * 4 + 1] = b.y; xB[j * 4 + 2] = b.z; xB[j * 4 + 3] = b.w;
        }
        #pragma unroll
        for (int h = 0; h < HH; h++) {
            float scA = 0.f, scB = 0.f;
            #pragma unroll
            for (int c = 0; c < OUTC; c++) {
                float v;
                v = xA[h * OUTC + c] + xrv[h * OUTC + c];
                v = v > 0.f ? v : 0.2f * v;
                scA += v * attv[h * OUTC + c];
                v = xB[h * OUTC + c] + xrv[h * OUTC + c];
                v = v > 0.f ? v : 0.2f * v;
                scB += v * attv[h * OUTC + c];
            }
            float eA = __expf(scA), eB = __expf(scB);
            dn[h] += eA + eB;
            #pragma unroll
            for (int c = 0; c < OUTC; c++)
                acc[h * OUTC + c] += eA * xA[h * OUTC + c] + eB * xB[h * OUTC + c];
        }
    }
    for (; i < s1; i++) {
        int s = elist[i];
        float xlv[FHC];
        const float4* p = (const float4*)(fxl + (size_t)s * FHC);
        #pragma unroll
        for (int j = 0; j < 5; j++) {
            float4 a = p[j];
            xlv[j * 4 + 0] = a.x; xlv[j * 4 + 1] = a.y; xlv[j * 4 + 2] = a.z; xlv[j * 4 + 3] = a.w;
        }
        #pragma unroll
        for (int h = 0; h < HH; h++) {
            float sc = 0.f;
            #pragma unroll
            for (int c = 0; c < OUTC; c++) {
                float v = xlv[h * OUTC + c] + xrv[h * OUTC + c];
                v = v > 0.f ? v : 0.2f * v;
                sc += v * attv[h * OUTC + c];
            }
            float e = __expf(sc);
            dn[h] += e;
            #pragma unroll
            for (int c = 0; c < OUTC; c++) acc[h * OUTC + c] += e * xlv[h * OUTC + c];
        }
    }

    float inv[HH];
    #pragma unroll
    for (int h = 0; h < HH; h++) inv[h] = 1.f / (dn[h] + 1e-16f);

    float v[OUTC];
    #pragma unroll
    for (int c = 0; c < OUTC; c++) {
        float s = 0.f;
        #pragma unroll
        for (int h = 0; h < HH; h++) s += acc[h * OUTC + c] * inv[h];
        v[c] = 0.25f * s + fbconv[c] + linv[c];
    }
    float mx = v[0];
    #pragma unroll
    for (int c = 1; c < OUTC; c++) mx = fmaxf(mx, v[c]);
    float se = 0.f;
    #pragma unroll
    for (int c = 0; c < OUTC; c++) se += expf(v[c] - mx);
    float lse = logf(se);
    #pragma unroll
    for (int c = 0; c < OUTC; c++) out[(size_t)n * OUTC + c] = v[c] - mx - lse;
}

// ---------------- host launcher ----------------
extern "C" void kernel_launch(void* const* d_in, const int* in_sizes, int n_in,
                              void* d_out, int out_size)
{
    const float* x      = (const float*)d_in[0];
    const int*   ei     = (const int*)d_in[1];
    const float* Wl     = (const float*)d_in[2];
    const float* Wr     = (const float*)d_in[3];
    const float* att    = (const float*)d_in[4];
    const float* bconv  = (const float*)d_in[5];
    const float* Wlin   = (const float*)d_in[6];
    const float* blin   = (const float*)d_in[7];
    const float* gn_w   = (const float*)d_in[8];
    const float* gn_b   = (const float*)d_in[9];
    const float* gn_ms  = (const float*)d_in[10];
    const float* fWl    = (const float*)d_in[11];
    const float* fWr    = (const float*)d_in[12];
    const float* fatt   = (const float*)d_in[13];
    const float* fbconv = (const float*)d_in[14];
    const float* fWlin  = (const float*)d_in[15];
    const float* fblin  = (const float*)d_in[16];
    float* out = (float*)d_out;

    const int* src = ei;
    const int* dst = ei + EE;

    float *xl, *xr, *lin, *agg, *emb, *stats;
    int *rowptr, *cnt, *elist;
    __nv_bfloat16 *ahi, *alo, *bthi, *btlo;
    cudaGetSymbolAddress((void**)&xl, g_xl);
    cudaGetSymbolAddress((void**)&xr, g_xr);
    cudaGetSymbolAddress((void**)&lin, g_lin);
    cudaGetSymbolAddress((void**)&agg, g_agg);
    cudaGetSymbolAddress((void**)&emb, g_emb);
    cudaGetSymbolAddress((void**)&stats, g_stats);
    cudaGetSymbolAddress((void**)&rowptr, g_rowptr);
    cudaGetSymbolAddress((void**)&cnt, g_cnt);
    cudaGetSymbolAddress((void**)&elist, g_elist);
    cudaGetSymbolAddress((void**)&ahi, g_ahi);
    cudaGetSymbolAddress((void**)&alo, g_alo);
    cudaGetSymbolAddress((void**)&bthi, g_bthi);
    cudaGetSymbolAddress((void**)&btlo, g_btlo);

    static cudaStream_t s2 = nullptr, s3 = nullptr;
    static cudaEvent_t evFork = nullptr, evJoin = nullptr, evA = nullptr;
    if (!s2) {
        cudaStreamCreateWithFlags(&s2, cudaStreamNonBlocking);
        cudaStreamCreateWithFlags(&s3, cudaStreamNonBlocking);
        cudaEventCreateWithFlags(&evFork, cudaEventDisableTiming);
        cudaEventCreateWithFlags(&evJoin, cudaEventDisableTiming);
        cudaEventCreateWithFlags(&evA, cudaEventDisableTiming);
        cudaFuncSetAttribute(gemm_wide, cudaFuncAttributeMaxDynamicSharedMemorySize, GSM_TOTAL);
    }

    cudaEventRecord(evFork, 0);

    // ---- s2: CSR build + upfront stats zeroing (both layers) ----
    cudaStreamWaitEvent(s2, evFork, 0);
    cudaMemsetAsync(stats, 0, 4 * HC * sizeof(float), s2);
    cudaMemsetAsync(cnt, 0, NN * sizeof(int), s2);
    hist_kernel<<<(EE + 255) / 256, 256, 0, s2>>>(dst, cnt);
    scan_kernel<<<1, 1024, 0, s2>>>(cnt, rowptr);
    cudaMemsetAsync(cnt, 0, NN * sizeof(int), s2);
    scatter_kernel<<<(EE + 255) / 256, 256, 0, s2>>>(src, dst, rowptr, cnt, elist);
    cudaEventRecord(evJoin, s2);

    // ---- s3: A split ----
    cudaStreamWaitEvent(s3, evFork, 0);
    split_a_kernel<<<(NN * DD + 255) / 256, 256, 0, s3>>>(x, ahi, alo, NN * DD);
    cudaEventRecord(evA, s3);

    dim3 gGemm(6, (NN + 127) / 128);
    dim3 gSplitB(DD * HC / 256, 6);
    const int nodeBlocks = (NN + 7) / 8;

    // ---- default stream ----
    split_bt6_kernel<<<gSplitB, 256>>>(Wl, Wr, Wlin, bthi, btlo);
    cudaStreamWaitEvent(0, evA, 0);

    for (int i = 0; i < 2; i++) {
        gemm_wide<<<gGemm, 256, GSM_TOTAL>>>(ahi, alo,
            bthi + (size_t)i * 3 * DD * HC, btlo + (size_t)i * 3 * DD * HC,
            blin + (size_t)i * HC, xl, xr, lin, NN);

        if (i == 0) cudaStreamWaitEvent(0, evJoin, 0);

        float* statsL = stats + (size_t)i * 2 * HC;
        node_attn_kernel<<<nodeBlocks, 256>>>(xl, xr, att + (size_t)i * HC, rowptr, elist,
                                              agg, statsL);
        norm_elu_kernel<<<(NN * HC + 255) / 256, 256>>>(
            agg, lin, bconv + (size_t)i * HC, gn_w + (size_t)i * HC,
            gn_b + (size_t)i * HC, gn_ms + (size_t)i * HC, statsL, emb,
            ahi, alo, (i == 0) ? 1 : 0);
    }

    final_proj_kernel<<<600, 256>>>(emb, fWl, fWr, fWlin, fblin, xl, xr, lin);
    final_fused_kernel<<<(NN + 255) / 256, 256>>>(xl, xr, fatt, rowptr, elist, lin, fbconv, out);
}

// round 16
// speedup vs baseline: 1.0871x; 1.0871x over previous
#include <cuda_runtime.h>
#include <cuda_bf16.h>
#include <math.h>
#include <stdint.h>

#define NN 50000
#define EE 800000
#define DD 256
#define HH 4
#define HC 256      // H*C
#define OUTC 5
#define FHC 20      // H*OUT

// ---------------- scratch (static device globals) ----------------
__device__ float g_xl[(size_t)NN * HC];
__device__ float g_xr[(size_t)NN * HC];
__device__ float g_lin[(size_t)NN * HC];
__device__ float g_agg[(size_t)NN * HC];
__device__ float g_emb[(size_t)NN * HC];
__device__ float g_stats[4 * HC];          // 2 layers x (sum, sumsq)
__device__ int   g_rowptr[NN + 1];
__device__ int   g_cnt[NN];
__device__ int   g_elist[EE];
__device__ __nv_bfloat16 g_ahi[(size_t)NN * DD];
__device__ __nv_bfloat16 g_alo[(size_t)NN * DD];
__device__ __nv_bfloat16 g_bthi[6 * DD * HC];
__device__ __nv_bfloat16 g_btlo[6 * DD * HC];

// ---------------- CSR build ----------------
__global__ void hist_kernel(const int* __restrict__ dst, int* __restrict__ cnt) {
    int e = blockIdx.x * blockDim.x + threadIdx.x;
    if (e < EE) atomicAdd(&cnt[dst[e]], 1);
}

__global__ void scan_kernel(const int* __restrict__ cnt, int* __restrict__ rowptr) {
    __shared__ int sh[1024];
    __shared__ int offs;
    if (threadIdx.x == 0) { offs = 0; rowptr[0] = 0; }
    __syncthreads();
    for (int base = 0; base < NN; base += 1024) {
        int i = base + threadIdx.x;
        int v = (i < NN) ? cnt[i] : 0;
        sh[threadIdx.x] = v;
        __syncthreads();
        #pragma unroll
        for (int off = 1; off < 1024; off <<= 1) {
            int t = (threadIdx.x >= off) ? sh[threadIdx.x - off] : 0;
            __syncthreads();
            sh[threadIdx.x] += t;
            __syncthreads();
        }
        if (i < NN) rowptr[i + 1] = sh[threadIdx.x] + offs;
        __syncthreads();
        if (threadIdx.x == 1023) offs += sh[1023];
        __syncthreads();
    }
}

__global__ void scatter_kernel(const int* __restrict__ src, const int* __restrict__ dst,
                               const int* __restrict__ rowptr, int* __restrict__ cnt,
                               int* __restrict__ elist) {
    int e = blockIdx.x * blockDim.x + threadIdx.x;
    if (e >= EE) return;
    int d = dst[e];
    int pos = rowptr[d] + atomicAdd(&cnt[d], 1);
    elist[pos] = src[e];
}

// ---------------- bf16 split kernels ----------------
__global__ void split_a_kernel(const float* __restrict__ A,
                               __nv_bfloat16* __restrict__ hi, __nv_bfloat16* __restrict__ lo,
                               int n) {
    int i = blockIdx.x * blockDim.x + threadIdx.x;
    if (i >= n) return;
    float v = A[i];
    __nv_bfloat16 h = __float2bfloat16(v);
    hi[i] = h;
    lo[i] = __float2bfloat16(v - __bfloat162float(h));
}

__global__ void split_bt6_kernel(const float* __restrict__ Wl, const float* __restrict__ Wr,
                                 const float* __restrict__ Wlin,
                                 __nv_bfloat16* __restrict__ hi, __nv_bfloat16* __restrict__ lo) {
    int i = blockIdx.x * blockDim.x + threadIdx.x;   // 65536
    int m = blockIdx.y;                               // 0..5
    int layer = m / 3, which = m % 3;
    const float* B = (which == 0) ? Wl : (which == 1) ? Wr : Wlin;
    B += (size_t)layer * DD * HC;
    int k = i >> 8, n = i & 255;
    float v = B[k * 256 + n];
    __nv_bfloat16 h = __float2bfloat16(v);
    size_t o = (size_t)m * DD * HC + (size_t)n * 256 + k;
    hi[o] = h;
    lo[o] = __float2bfloat16(v - __bfloat162float(h));
}

// ---------------- mma.sync helpers ----------------
__device__ __forceinline__ void mma_bf16(float* d, const uint32_t* a, uint32_t b0, uint32_t b1) {
    asm volatile(
        "mma.sync.aligned.m16n8k16.row.col.f32.bf16.bf16.f32 "
        "{%0,%1,%2,%3}, {%4,%5,%6,%7}, {%8,%9}, {%0,%1,%2,%3};"
        : "+f"(d[0]), "+f"(d[1]), "+f"(d[2]), "+f"(d[3])
        : "r"(a[0]), "r"(a[1]), "r"(a[2]), "r"(a[3]), "r"(b0), "r"(b1));
}
__device__ __forceinline__ void ldsm4a(uint32_t* r, uint32_t addr) {
    asm volatile("ldmatrix.sync.aligned.m8n8.x4.shared.b16 {%0,%1,%2,%3}, [%4];"
        : "=r"(r[0]), "=r"(r[1]), "=r"(r[2]), "=r"(r[3]) : "r"(addr));
}
__device__ __forceinline__ void cp16(uint32_t dst, const void* src, bool pred) {
    int sz = pred ? 16 : 0;
    asm volatile("cp.async.ca.shared.global [%0], [%1], 16, %2;"
                 :: "r"(dst), "l"(src), "r"(sz));
}
__device__ __forceinline__ void cp_commit() {
    asm volatile("cp.async.commit_group;" ::: "memory");
}
template <int N>
__device__ __forceinline__ void cp_wait() {
    asm volatile("cp.async.wait_group %0;" :: "n"(N) : "memory");
}

// ---------------- GEMM: fused N=768, 128x128 tiles, cp.async, KT=32, 3xBF16 ----------------
#define ROWB 80
#define OFF_ALO (128 * ROWB)
#define OFF_BHI (2 * 128 * ROWB)
#define OFF_BLO (3 * 128 * ROWB)
#define STAGE_B (4 * 128 * ROWB)      // 40960
#define GSM_TOTAL (2 * STAGE_B)       // 81920

__global__ __launch_bounds__(256, 2) void gemm_wide(
    const __nv_bfloat16* __restrict__ Ahi, const __nv_bfloat16* __restrict__ Alo,
    const __nv_bfloat16* __restrict__ Bthi, const __nv_bfloat16* __restrict__ Btlo,
    const float* __restrict__ blin,
    float* __restrict__ C0, float* __restrict__ C1, float* __restrict__ C2, int M)
{
    extern __shared__ char smraw[];
    const uint32_t sb = (uint32_t)__cvta_generic_to_shared(smraw);

    const int tid = threadIdx.x;
    const int bx = blockIdx.x, by = blockIdx.y;
    const int n0 = bx * 128;
    const int mat = n0 >> 8;
    const int cbase = n0 & 255;
    float* C = (mat == 0) ? C0 : (mat == 1) ? C1 : C2;

    const __nv_bfloat16* Bh = Bthi + (size_t)n0 * DD;
    const __nv_bfloat16* Bl = Btlo + (size_t)n0 * DD;

    const int lane = tid & 31, wid = tid >> 5;
    const int warpM = wid >> 1;
    const int warpN = wid & 1;
    const int g = lane >> 2, t = lane & 3;
    const int lr = lane & 15;
    const uint32_t lkB = (uint32_t)((lane >> 4) * 16);

    const int ldRow = tid >> 1;
    const int ldHalf = (tid & 1) * 32;

    const int gARow = by * 128 + ldRow;
    const bool aOK = (gARow < M);
    const __nv_bfloat16* Aph = Ahi + (size_t)gARow * DD;
    const __nv_bfloat16* Apl = Alo + (size_t)gARow * DD;
    const __nv_bfloat16* Bph = Bh + (size_t)ldRow * DD;
    const __nv_bfloat16* Bpl = Bl + (size_t)ldRow * DD;

    float acc[2][8][4];
    #pragma unroll
    for (int mi = 0; mi < 2; mi++)
        #pragma unroll
        for (int ni = 0; ni < 8; ni++)
            #pragma unroll
            for (int r = 0; r < 4; r++) acc[mi][ni][r] = 0.f;

    auto issue = [&](int kt, int stage) {
        const int k0 = kt * 32;
        const uint32_t s = sb + (uint32_t)stage * STAGE_B;
        uint32_t roff = (uint32_t)(ldRow * ROWB + ldHalf);
        const int ke = k0 + ldHalf / 2;
        cp16(s + roff,                Aph + ke,     aOK);
        cp16(s + roff + 16,           Aph + ke + 8, aOK);
        cp16(s + OFF_ALO + roff,      Apl + ke,     aOK);
        cp16(s + OFF_ALO + roff + 16, Apl + ke + 8, aOK);
        cp16(s + OFF_BHI + roff,      Bph + ke,     true);
        cp16(s + OFF_BHI + roff + 16, Bph + ke + 8, true);
        cp16(s + OFF_BLO + roff,      Bpl + ke,     true);
        cp16(s + OFF_BLO + roff + 16, Bpl + ke + 8, true);
        cp_commit();
    };

    issue(0, 0);

    const int NT = DD / 32;   // 8
    for (int kt = 0; kt < NT; kt++) {
        const int cur = kt & 1;
        cp_wait<0>();
        __syncthreads();
        if (kt + 1 < NT) issue(kt + 1, (kt + 1) & 1);   // overlaps with compute below

        const uint32_t s = sb + (uint32_t)cur * STAGE_B;
        #pragma unroll
        for (int ks2 = 0; ks2 < 2; ks2++) {
            const uint32_t kb = (uint32_t)(ks2 * 32) + lkB;
            uint32_t ah[2][4], al[2][4];
            #pragma unroll
            for (int mi = 0; mi < 2; mi++) {
                uint32_t r = (uint32_t)((warpM * 32 + mi * 16 + lr) * ROWB) + kb;
                ldsm4a(ah[mi], s + r);
                ldsm4a(al[mi], s + OFF_ALO + r);
            }
            #pragma unroll
            for (int p = 0; p < 4; p++) {
                uint32_t r = (uint32_t)((warpN * 64 + p * 16 + lr) * ROWB) + kb;
                uint32_t th[4], tl[4];
                ldsm4a(th, s + OFF_BHI + r);
                ldsm4a(tl, s + OFF_BLO + r);
                #pragma unroll
                for (int mi = 0; mi < 2; mi++) {
                    mma_bf16(acc[mi][2 * p],     ah[mi], th[0], th[2]);
                    mma_bf16(acc[mi][2 * p],     ah[mi], tl[0], tl[2]);
                    mma_bf16(acc[mi][2 * p],     al[mi], th[0], th[2]);
                    mma_bf16(acc[mi][2 * p + 1], ah[mi], th[1], th[3]);
                    mma_bf16(acc[mi][2 * p + 1], ah[mi], tl[1], tl[3]);
                    mma_bf16(acc[mi][2 * p + 1], al[mi], th[1], th[3]);
                }
            }
        }
    }

    #pragma unroll
    for (int mi = 0; mi < 2; mi++) {
        int r0 = by * 128 + warpM * 32 + mi * 16 + g;
        #pragma unroll
        for (int ni = 0; ni < 8; ni++) {
            int ccol = cbase + warpN * 64 + ni * 8 + t * 2;
            float b0 = (mat == 2) ? blin[ccol] : 0.f;
            float b1 = (mat == 2) ? blin[ccol + 1] : 0.f;
            if (r0 < M)
                *(float2*)(C + (size_t)r0 * 256 + ccol) =
                    make_float2(acc[mi][ni][0] + b0, acc[mi][ni][1] + b1);
            if (r0 + 8 < M)
                *(float2*)(C + (size_t)(r0 + 8) * 256 + ccol) =
                    make_float2(acc[mi][ni][2] + b0, acc[mi][ni][3] + b1);
        }
    }
}

// ---------------- CSR node-centric attention (warp per dst node) + fused stats ----------------
__global__ __launch_bounds__(256) void node_attn_kernel(
    const float* __restrict__ xl, const float* __restrict__ xr,
    const float* __restrict__ att,
    const int* __restrict__ rowptr, const int* __restrict__ elist,
    float* __restrict__ aggout, float* __restrict__ stats)
{
    __shared__ float sstat[2][HC];
    for (int i = threadIdx.x; i < 2 * HC; i += 256) ((float*)sstat)[i] = 0.f;
    __syncthreads();

    int n = (blockIdx.x * blockDim.x + threadIdx.x) >> 5;
    int lane = threadIdx.x & 31;
    const int base = lane * 8;

    float xrv[8], attv[8];
    {
        const float4* p = (const float4*)(xr + (size_t)n * HC + base);
        float4 r0 = p[0], r1 = p[1];
        xrv[0] = r0.x; xrv[1] = r0.y; xrv[2] = r0.z; xrv[3] = r0.w;
        xrv[4] = r1.x; xrv[5] = r1.y; xrv[6] = r1.z; xrv[7] = r1.w;
        const float4* q = (const float4*)(att + base);
        float4 a0 = q[0], a1 = q[1];
        attv[0] = a0.x; attv[1] = a0.y; attv[2] = a0.z; attv[3] = a0.w;
        attv[4] = a1.x; attv[5] = a1.y; attv[6] = a1.z; attv[7] = a1.w;
    }

    float acc[8] = {0.f, 0.f, 0.f, 0.f, 0.f, 0.f, 0.f, 0.f};
    float dn = 0.f;
    const int s0 = rowptr[n], s1 = rowptr[n + 1];
    int i = s0;
    for (; i + 3 < s1; i += 4) {
        int e0 = elist[i], e1 = elist[i + 1], e2 = elist[i + 2], e3 = elist[i + 3];
        const float4* p0 = (const float4*)(xl + (size_t)e0 * HC + base);
        const float4* p1 = (const float4*)(xl + (size_t)e1 * HC + base);
        const float4* p2 = (const float4*)(xl + (size_t)e2 * HC + base);
        const float4* p3 = (const float4*)(xl + (size_t)e3 * HC + base);
        float4 a0 = p0[0], b0 = p0[1];
        float4 a1 = p1[0], b1 = p1[1];
        float4 a2 = p2[0], b2 = p2[1];
        float4 a3 = p3[0], b3 = p3[1];
        float x0[8] = {a0.x, a0.y, a0.z, a0.w, b0.x, b0.y, b0.z, b0.w};
        float x1[8] = {a1.x, a1.y, a1.z, a1.w, b1.x, b1.y, b1.z, b1.w};
        float x2[8] = {a2.x, a2.y, a2.z, a2.w, b2.x, b2.y, b2.z, b2.w};
        float x3[8] = {a3.x, a3.y, a3.z, a3.w, b3.x, b3.y, b3.z, b3.w};
        float c0 = 0.f, c1 = 0.f, c2 = 0.f, c3 = 0.f;
        #pragma unroll
        for (int t = 0; t < 8; t++) {
            float v;
            v = x0[t] + xrv[t]; v = v > 0.f ? v : 0.2f * v; c0 += v * attv[t];
            v = x1[t] + xrv[t]; v = v > 0.f ? v : 0.2f * v; c1 += v * attv[t];
            v = x2[t] + xrv[t]; v = v > 0.f ? v : 0.2f * v; c2 += v * attv[t];
            v = x3[t] + xrv[t]; v = v > 0.f ? v : 0.2f * v; c3 += v * attv[t];
        }
        #pragma unroll
        for (int d = 4; d >= 1; d >>= 1) {
            c0 += __shfl_xor_sync(0xffffffffu, c0, d);
            c1 += __shfl_xor_sync(0xffffffffu, c1, d);
            c2 += __shfl_xor_sync(0xffffffffu, c2, d);
            c3 += __shfl_xor_sync(0xffffffffu, c3, d);
        }
        float w0 = __expf(c0), w1 = __expf(c1), w2 = __expf(c2), w3 = __expf(c3);
        dn += (w0 + w1) + (w2 + w3);
        #pragma unroll
        for (int t = 0; t < 8; t++)
            acc[t] += (w0 * x0[t] + w1 * x1[t]) + (w2 * x2[t] + w3 * x3[t]);
    }
    for (; i < s1; i++) {
        int e0 = elist[i];
        const float4* p = (const float4*)(xl + (size_t)e0 * HC + base);
        float4 a0 = p[0], b0 = p[1];
        float x0[8] = {a0.x, a0.y, a0.z, a0.w, b0.x, b0.y, b0.z, b0.w};
        float sc = 0.f;
        #pragma unroll
        for (int t = 0; t < 8; t++) {
            float v = x0[t] + xrv[t];
            v = v > 0.f ? v : 0.2f * v;
            sc += v * attv[t];
        }
        sc += __shfl_xor_sync(0xffffffffu, sc, 4);
        sc += __shfl_xor_sync(0xffffffffu, sc, 2);
        sc += __shfl_xor_sync(0xffffffffu, sc, 1);
        float e = __expf(sc);
        dn += e;
        #pragma unroll
        for (int t = 0; t < 8; t++) acc[t] += e * x0[t];
    }

    float inv = 1.f / (dn + 1e-16f);
    float o[8];
    #pragma unroll
    for (int t = 0; t < 8; t++) o[t] = acc[t] * inv;

    float4* op = (float4*)(aggout + (size_t)n * HC + base);
    op[0] = make_float4(o[0], o[1], o[2], o[3]);
    op[1] = make_float4(o[4], o[5], o[6], o[7]);

    #pragma unroll
    for (int t = 0; t < 8; t++) {
        atomicAdd(&sstat[0][base + t], o[t]);
        atomicAdd(&sstat[1][base + t], o[t] * o[t]);
    }
    __syncthreads();
    for (int c = threadIdx.x; c < HC; c += 256) {
        atomicAdd(&stats[c], sstat[0][c]);
        atomicAdd(&stats[HC + c], sstat[1][c]);
    }
}

// ---------------- GraphNorm epilogue ----------------
__global__ void norm_elu_kernel(
    const float* __restrict__ agg, const float* __restrict__ lin,
    const float* __restrict__ bias, const float* __restrict__ gw,
    const float* __restrict__ gb, const float* __restrict__ ms,
    const float* __restrict__ stats, float* __restrict__ out,
    __nv_bfloat16* __restrict__ hi, __nv_bfloat16* __restrict__ lo, int writeSplit)
{
    int idx = blockIdx.x * blockDim.x + threadIdx.x;
    if (idx >= NN * HC) return;
    int c = idx & 255;
    const float invn = 1.f / (float)NN;
    float b = bias[c];
    float s1 = stats[c] * invn;
    float s2 = stats[HC + c] * invn;
    float mean = s1 + b;
    float ey2 = s2 + 2.f * b * s1 + b * b;
    float msv = ms[c];
    float var = ey2 - 2.f * mean * msv * mean + mean * mean * msv * msv;
    float y = agg[idx] + b;
    float centered = y - mean * msv;
    float v = gw[c] * centered * rsqrtf(var + 1e-5f) + gb[c] + lin[idx];
    v = v > 0.f ? v : expm1f(v);
    out[idx] = v;
    if (writeSplit) {
        __nv_bfloat16 h = __float2bfloat16(v);
        hi[idx] = h;
        lo[idx] = __float2bfloat16(v - __bfloat162float(h));
    }
}

// ---------------- fused final projections (45 cols) ----------------
__global__ __launch_bounds__(256) void final_proj_kernel(
    const float* __restrict__ emb, const float* __restrict__ fWl,
    const float* __restrict__ fWr, const float* __restrict__ fWlin,
    const float* __restrict__ fblin,
    float* __restrict__ xl, float* __restrict__ xr, float* __restrict__ lin)
{
    __shared__ float Bs[DD][45];
    for (int i = threadIdx.x; i < DD * FHC; i += 256) {
        int k = i / FHC, c = i % FHC;
        Bs[k][c] = fWl[i];
        Bs[k][FHC + c] = fWr[i];
    }
    for (int i = threadIdx.x; i < DD * OUTC; i += 256) {
        int k = i / OUTC, c = i % OUTC;
        Bs[k][2 * FHC + c] = fWlin[i];
    }
    __syncthreads();

    int lane = threadIdx.x & 31;
    int warp = threadIdx.x >> 5;
    int nwarp = gridDim.x * 8;
    for (int row = blockIdx.x * 8 + warp; row < NN; row += nwarp) {
        float acc[45];
        #pragma unroll
        for (int c = 0; c < 45; c++) acc[c] = 0.f;
        #pragma unroll
        for (int i = 0; i < 8; i++) {
            float a = emb[(size_t)row * DD + i * 32 + lane];
            const float* bp = &Bs[i * 32 + lane][0];
            #pragma unroll
            for (int c = 0; c < 45; c++) acc[c] += a * bp[c];
        }
        #pragma unroll
        for (int c = 0; c < 45; c++) {
            float v = acc[c];
            v += __shfl_xor_sync(0xffffffffu, v, 16);
            v += __shfl_xor_sync(0xffffffffu, v, 8);
            v += __shfl_xor_sync(0xffffffffu, v, 4);
            v += __shfl_xor_sync(0xffffffffu, v, 2);
            v += __shfl_xor_sync(0xffffffffu, v, 1);
            acc[c] = v;
        }
        if (lane == 0) {
            #pragma unroll
            for (int c = 0; c < FHC; c++) xl[(size_t)row * FHC + c] = acc[c];
            #pragma unroll
            for (int c = 0; c < FHC; c++) xr[(size_t)row * FHC + c] = acc[FHC + c];
            #pragma unroll
            for (int c = 0; c < OUTC; c++) lin[(size_t)row * OUTC + c] = acc[2 * FHC + c] + fblin[c];
        }
    }
}

// ---------------- fused final attention + head-mean + log_softmax (thread per node) ----------------
__global__ void final_fused_kernel(
    const float* __restrict__ fxl, const float* __restrict__ fxr,
    const float* __restrict__ fatt,
    const int* __restrict__ rowptr, const int* __restrict__ elist,
    const float* __restrict__ lin, const float* __restrict__ fbconv,
    float* __restrict__ out)
{
    int n = blockIdx.x * blockDim.x + threadIdx.x;
    if (n >= NN) return;

    float linv[OUTC];
    #pragma unroll
    for (int c = 0; c < OUTC; c++) linv[c] = lin[(size_t)n * OUTC + c];

    float xrv[FHC], attv[FHC];
    {
        const float4* p = (const float4*)(fxr + (size_t)n * FHC);
        const float4* q = (const float4*)fatt;
        #pragma unroll
        for (int j = 0; j < 5; j++) {
            float4 a = p[j], b = q[j];
            xrv[j * 4 + 0] = a.x; xrv[j * 4 + 1] = a.y; xrv[j * 4 + 2] = a.z; xrv[j * 4 + 3] = a.w;
            attv[j * 4 + 0] = b.x; attv[j * 4 + 1] = b.y; attv[j * 4 + 2] = b.z; attv[j * 4 + 3] = b.w;
        }
    }

    float acc[FHC];
    #pragma unroll
    for (int c = 0; c < FHC; c++) acc[c] = 0.f;
    float dn[HH] = {0.f, 0.f, 0.f, 0.f};

    const int s0 = rowptr[n], s1 = rowptr[n + 1];
    int i = s0;
    for (; i + 1 < s1; i += 2) {
        int sA = elist[i], sB = elist[i + 1];
        float xA[FHC], xB[FHC];
        const float4* pA = (const float4*)(fxl + (size_t)sA * FHC);
        const float4* pB = (const float4*)(fxl + (size_t)sB * FHC);
        #pragma unroll
        for (int j = 0; j < 5; j++) {
            float4 a = pA[j], b = pB[j];
            xA[j * 4 + 0] = a.x; xA[j * 4 + 1] = a.y; xA[j * 4 + 2] = a.z; xA[j * 4 + 3] = a.w;
            xB[j * 4 + 0] = b.x; xB[j * 4 + 1] = b.y; xB[j * 4 + 2] = b.z; xB[j * 4 + 3] = b.w;
        }
        #pragma unroll
        for (int h = 0; h < HH; h++) {
            float scA = 0.f, scB = 0.f;
            #pragma unroll
            for (int c = 0; c < OUTC; c++) {
                float v;
                v = xA[h * OUTC + c] + xrv[h * OUTC + c];
                v = v > 0.f ? v : 0.2f * v;
                scA += v * attv[h * OUTC + c];
                v = xB[h * OUTC + c] + xrv[h * OUTC + c];
                v = v > 0.f ? v : 0.2f * v;
                scB += v * attv[h * OUTC + c];
            }
            float eA = __expf(scA), eB = __expf(scB);
            dn[h] += eA + eB;
            #pragma unroll
            for (int c = 0; c < OUTC; c++)
                acc[h * OUTC + c] += eA * xA[h * OUTC + c] + eB * xB[h * OUTC + c];
        }
    }
    for (; i < s1; i++) {
        int s = elist[i];
        float xlv[FHC];
        const float4* p = (const float4*)(fxl + (size_t)s * FHC);
        #pragma unroll
        for (int j = 0; j < 5; j++) {
            float4 a = p[j];
            xlv[j * 4 + 0] = a.x; xlv[j * 4 + 1] = a.y; xlv[j * 4 + 2] = a.z; xlv[j * 4 + 3] = a.w;
        }
        #pragma unroll
        for (int h = 0; h < HH; h++) {
            float sc = 0.f;
            #pragma unroll
            for (int c = 0; c < OUTC; c++) {
                float v = xlv[h * OUTC + c] + xrv[h * OUTC + c];
                v = v > 0.f ? v : 0.2f * v;
                sc += v * attv[h * OUTC + c];
            }
            float e = __expf(sc);
            dn[h] += e;
            #pragma unroll
            for (int c = 0; c < OUTC; c++) acc[h * OUTC + c] += e * xlv[h * OUTC + c];
        }
    }

    float inv[HH];
    #pragma unroll
    for (int h = 0; h < HH; h++) inv[h] = 1.f / (dn[h] + 1e-16f);

    float v[OUTC];
    #pragma unroll
    for (int c = 0; c < OUTC; c++) {
        float s = 0.f;
        #pragma unroll
        for (int h = 0; h < HH; h++) s += acc[h * OUTC + c] * inv[h];
        v[c] = 0.25f * s + fbconv[c] + linv[c];
    }
    float mx = v[0];
    #pragma unroll
    for (int c = 1; c < OUTC; c++) mx = fmaxf(mx, v[c]);
    float se = 0.f;
    #pragma unroll
    for (int c = 0; c < OUTC; c++) se += expf(v[c] - mx);
    float lse = logf(se);
    #pragma unroll
    for (int c = 0; c < OUTC; c++) out[(size_t)n * OUTC + c] = v[c] - mx - lse;
}

// ---------------- host launcher ----------------
extern "C" void kernel_launch(void* const* d_in, const int* in_sizes, int n_in,
                              void* d_out, int out_size)
{
    const float* x      = (const float*)d_in[0];
    const int*   ei     = (const int*)d_in[1];
    const float* Wl     = (const float*)d_in[2];
    const float* Wr     = (const float*)d_in[3];
    const float* att    = (const float*)d_in[4];
    const float* bconv  = (const float*)d_in[5];
    const float* Wlin   = (const float*)d_in[6];
    const float* blin   = (const float*)d_in[7];
    const float* gn_w   = (const float*)d_in[8];
    const float* gn_b   = (const float*)d_in[9];
    const float* gn_ms  = (const float*)d_in[10];
    const float* fWl    = (const float*)d_in[11];
    const float* fWr    = (const float*)d_in[12];
    const float* fatt   = (const float*)d_in[13];
    const float* fbconv = (const float*)d_in[14];
    const float* fWlin  = (const float*)d_in[15];
    const float* fblin  = (const float*)d_in[16];
    float* out = (float*)d_out;

    const int* src = ei;
    const int* dst = ei + EE;

    float *xl, *xr, *lin, *agg, *emb, *stats;
    int *rowptr, *cnt, *elist;
    __nv_bfloat16 *ahi, *alo, *bthi, *btlo;
    cudaGetSymbolAddress((void**)&xl, g_xl);
    cudaGetSymbolAddress((void**)&xr, g_xr);
    cudaGetSymbolAddress((void**)&lin, g_lin);
    cudaGetSymbolAddress((void**)&agg, g_agg);
    cudaGetSymbolAddress((void**)&emb, g_emb);
    cudaGetSymbolAddress((void**)&stats, g_stats);
    cudaGetSymbolAddress((void**)&rowptr, g_rowptr);
    cudaGetSymbolAddress((void**)&cnt, g_cnt);
    cudaGetSymbolAddress((void**)&elist, g_elist);
    cudaGetSymbolAddress((void**)&ahi, g_ahi);
    cudaGetSymbolAddress((void**)&alo, g_alo);
    cudaGetSymbolAddress((void**)&bthi, g_bthi);
    cudaGetSymbolAddress((void**)&btlo, g_btlo);

    static cudaStream_t s2 = nullptr, s3 = nullptr;
    static cudaEvent_t evFork = nullptr, evJoin = nullptr, evA = nullptr;
    if (!s2) {
        cudaStreamCreateWithFlags(&s2, cudaStreamNonBlocking);
        cudaStreamCreateWithFlags(&s3, cudaStreamNonBlocking);
        cudaEventCreateWithFlags(&evFork, cudaEventDisableTiming);
        cudaEventCreateWithFlags(&evJoin, cudaEventDisableTiming);
        cudaEventCreateWithFlags(&evA, cudaEventDisableTiming);
        cudaFuncSetAttribute(gemm_wide, cudaFuncAttributeMaxDynamicSharedMemorySize, GSM_TOTAL);
    }

    cudaEventRecord(evFork, 0);

    // ---- s2: CSR build + upfront stats zeroing (both layers) ----
    cudaStreamWaitEvent(s2, evFork, 0);
    cudaMemsetAsync(stats, 0, 4 * HC * sizeof(float), s2);
    cudaMemsetAsync(cnt, 0, NN * sizeof(int), s2);
    hist_kernel<<<(EE + 255) / 256, 256, 0, s2>>>(dst, cnt);
    scan_kernel<<<1, 1024, 0, s2>>>(cnt, rowptr);
    cudaMemsetAsync(cnt, 0, NN * sizeof(int), s2);
    scatter_kernel<<<(EE + 255) / 256, 256, 0, s2>>>(src, dst, rowptr, cnt, elist);
    cudaEventRecord(evJoin, s2);

    // ---- s3: A split ----
    cudaStreamWaitEvent(s3, evFork, 0);
    split_a_kernel<<<(NN * DD + 255) / 256, 256, 0, s3>>>(x, ahi, alo, NN * DD);
    cudaEventRecord(evA, s3);

    dim3 gGemm(6, (NN + 127) / 128);
    dim3 gSplitB(DD * HC / 256, 6);
    const int nodeBlocks = (NN + 7) / 8;

    // ---- default stream ----
    split_bt6_kernel<<<gSplitB, 256>>>(Wl, Wr, Wlin, bthi, btlo);
    cudaStreamWaitEvent(0, evA, 0);

    for (int i = 0; i < 2; i++) {
        gemm_wide<<<gGemm, 256, GSM_TOTAL>>>(ahi, alo,
            bthi + (size_t)i * 3 * DD * HC, btlo + (size_t)i * 3 * DD * HC,
            blin + (size_t)i * HC, xl, xr, lin, NN);

        if (i == 0) cudaStreamWaitEvent(0, evJoin, 0);

        float* statsL = stats + (size_t)i * 2 * HC;
        node_attn_kernel<<<nodeBlocks, 256>>>(xl, xr, att + (size_t)i * HC, rowptr, elist,
                                              agg, statsL);
        norm_elu_kernel<<<(NN * HC + 255) / 256, 256>>>(
            agg, lin, bconv + (size_t)i * HC, gn_w + (size_t)i * HC,
            gn_b + (size_t)i * HC, gn_ms + (size_t)i * HC, statsL, emb,
            ahi, alo, (i == 0) ? 1 : 0);
    }

    final_proj_kernel<<<600, 256>>>(emb, fWl, fWr, fWlin, fblin, xl, xr, lin);
    final_fused_kernel<<<(NN + 255) / 256, 256>>>(xl, xr, fatt, rowptr, elist, lin, fbconv, out);
}